// round 1
// baseline (speedup 1.0000x reference)
#include <cuda_runtime.h>
#include <cuda_bf16.h>

// ---------------------------------------------------------------------------
// PointerNet additive attention, B=4, Te=Td=512, E=256, D+E=512, H=64.
// out[b,d,t] = softmax_t( sum_h w2[h]*tanh(dec_t[b,d,h] + ctx_t[b,t,h]) + b2 )
//
// Kernel A: projections, pre-scaled by 2*log2(e) so kernel B can use
//           tanh(x) = (e^{2x}-1)/(e^{2x}+1) with a single ex2.approx.
//           ctx projection stored TRANSPOSED [b][h][t] for coalesced reads.
// Kernel B: fused score + tanh + H-reduction + softmax. 148 blocks = 1 wave.
// ---------------------------------------------------------------------------

#define B_   4
#define TE_  512
#define TD_  512
#define E_   256
#define DK_  512   // D+E
#define H_   64

// 2*log2(e): ex2(SCALE*x) = e^{2x}
#define TANH_SCALE 2.8853900817779268f
#define LOG2E      1.4426950408889634f

// scratch (device globals: allocation-free)
__device__ float g_ctxT[B_ * H_ * TE_];   // [b][h][t], pre-scaled
__device__ float g_decS[B_ * TD_ * H_];   // [b*Td+d][h], pre-scaled

// ---------------------------------------------------------------------------
// Kernel A: fused projections.
//   blocks [0,43):  ctx rows, 48 rows/block, K=256
//   blocks [43,129): dec rows, 24 rows/block, K=512
// 256 threads: h = tid&63, row-group rg = tid>>6 (4 groups)
// ---------------------------------------------------------------------------
__global__ __launch_bounds__(256) void kernelA(
    const float* __restrict__ ctx,   // [4,512,256]
    const float* __restrict__ dec,   // [4,512,512]
    const float* __restrict__ W1i,   // [256,64]
    const float* __restrict__ b1i,   // [64]
    const float* __restrict__ W1h,   // [512,64]
    const float* __restrict__ b1h)   // [64]
{
    __shared__ float xs[12288];                       // 48KB tile (union)
    float4* xs4 = reinterpret_cast<float4*>(xs);

    const int tid = threadIdx.x;
    const int h   = tid & 63;
    const int rg  = tid >> 6;

    if (blockIdx.x < 43) {
        // ----- ctx projection: 48 rows of K=256 -----
        const int r0 = blockIdx.x * 48;
        const float4* src = reinterpret_cast<const float4*>(ctx);
        for (int i = tid; i < 48 * 64; i += 256) {     // 64 float4 per row
            int row = i >> 6;
            xs4[i] = (r0 + row < 2048) ? src[(size_t)(r0 + row) * 64 + (i & 63)]
                                       : make_float4(0.f, 0.f, 0.f, 0.f);
        }
        __syncthreads();

        float acc[12];
        #pragma unroll
        for (int r = 0; r < 12; r++) acc[r] = 0.f;

        for (int e = 0; e < 256; e += 4) {
            const float* wp = W1i + e * 64 + h;
            float w0 = wp[0], w1 = wp[64], w2v = wp[128], w3 = wp[192];
            #pragma unroll
            for (int r = 0; r < 12; r++) {
                float4 x = xs4[(rg * 12 + r) * 64 + (e >> 2)];
                acc[r] = fmaf(x.x, w0, acc[r]);
                acc[r] = fmaf(x.y, w1, acc[r]);
                acc[r] = fmaf(x.z, w2v, acc[r]);
                acc[r] = fmaf(x.w, w3, acc[r]);
            }
        }
        const float bias = b1i[h];
        #pragma unroll
        for (int r = 0; r < 12; r++) {
            int row = r0 + rg * 12 + r;
            if (row < 2048) {
                int b = row >> 9, t = row & 511;
                g_ctxT[((b << 6) + h) * 512 + t] = (acc[r] + bias) * TANH_SCALE;
            }
        }
    } else {
        // ----- dec projection: 24 rows of K=512 -----
        const int r0 = (blockIdx.x - 43) * 24;
        const float4* src = reinterpret_cast<const float4*>(dec);
        for (int i = tid; i < 24 * 128; i += 256) {    // 128 float4 per row
            int row = i >> 7;
            xs4[i] = (r0 + row < 2048) ? src[(size_t)(r0 + row) * 128 + (i & 127)]
                                       : make_float4(0.f, 0.f, 0.f, 0.f);
        }
        __syncthreads();

        float acc[6];
        #pragma unroll
        for (int r = 0; r < 6; r++) acc[r] = 0.f;

        for (int e = 0; e < 512; e += 4) {
            const float* wp = W1h + e * 64 + h;
            float w0 = wp[0], w1 = wp[64], w2v = wp[128], w3 = wp[192];
            #pragma unroll
            for (int r = 0; r < 6; r++) {
                float4 x = xs4[(rg * 6 + r) * 128 + (e >> 2)];
                acc[r] = fmaf(x.x, w0, acc[r]);
                acc[r] = fmaf(x.y, w1, acc[r]);
                acc[r] = fmaf(x.z, w2v, acc[r]);
                acc[r] = fmaf(x.w, w3, acc[r]);
            }
        }
        const float bias = b1h[h];
        #pragma unroll
        for (int r = 0; r < 6; r++) {
            int row = r0 + rg * 6 + r;
            if (row < 2048)
                g_decS[(size_t)row * 64 + h] = (acc[r] + bias) * TANH_SCALE;
        }
    }
}

// ---------------------------------------------------------------------------
// Kernel B: fused tanh-score + softmax.
// grid = 148 (4 batches x 37 d-tiles of 14, last tile has 8 valid rows).
// 512 threads: thread t owns encoder column t for all 14 decoder rows.
// ---------------------------------------------------------------------------
__device__ __forceinline__ float ex2_approx(float x) {
    float y; asm("ex2.approx.f32 %0, %1;" : "=f"(y) : "f"(x)); return y;
}
__device__ __forceinline__ float rcp_approx(float x) {
    float y; asm("rcp.approx.f32 %0, %1;" : "=f"(y) : "f"(x)); return y;
}
// input already scaled by 2*log2(e)
__device__ __forceinline__ float fast_tanh_scaled(float s) {
    float e = ex2_approx(s);             // = exp(2x)
    return (e - 1.f) * rcp_approx(e + 1.f);
}

__global__ __launch_bounds__(512) void kernelB(
    const float* __restrict__ w2,    // [64]
    const float* __restrict__ b2p,   // [1]
    float* __restrict__ out)         // [4,512,512]
{
    __shared__ float dec_sh[14 * 64];
    __shared__ float w2_sh[64];
    __shared__ float red[14 * 16];
    __shared__ float inv_sh[14];

    const int tid = threadIdx.x;
    const int b   = blockIdx.x / 37;
    const int ti  = blockIdx.x % 37;
    const int d0  = ti * 14;

    // load decoder tile (zero-fill past batch end) + w2
    for (int i = tid; i < 14 * 64; i += 512) {
        int r = i >> 6;
        dec_sh[i] = (d0 + r < 512) ? g_decS[((size_t)(b << 9) + d0) * 64 + i] : 0.f;
    }
    if (tid < 64) w2_sh[tid] = w2[tid];
    __syncthreads();

    const int t = tid;
    const float* cptr = g_ctxT + (size_t)(b << 6) * 512 + t;

    float acc[14];
    #pragma unroll
    for (int d = 0; d < 14; d++) acc[d] = 0.f;

    #pragma unroll 1
    for (int h = 0; h < 64; h += 4) {
        float c0 = cptr[(h + 0) * 512];
        float c1 = cptr[(h + 1) * 512];
        float c2 = cptr[(h + 2) * 512];
        float c3 = cptr[(h + 3) * 512];
        float4 w4 = *reinterpret_cast<const float4*>(&w2_sh[h]);
        #pragma unroll
        for (int d = 0; d < 14; d++) {
            float4 dv = *reinterpret_cast<const float4*>(&dec_sh[d * 64 + h]);
            acc[d] = fmaf(w4.x, fast_tanh_scaled(dv.x + c0), acc[d]);
            acc[d] = fmaf(w4.y, fast_tanh_scaled(dv.y + c1), acc[d]);
            acc[d] = fmaf(w4.z, fast_tanh_scaled(dv.z + c2), acc[d]);
            acc[d] = fmaf(w4.w, fast_tanh_scaled(dv.w + c3), acc[d]);
        }
    }

    // softmax over t (scores bounded by sum|w2| ~ 6, no max-shift needed)
    const float b2v = b2p[0];
    const int wid = tid >> 5, lane = tid & 31;
    float ex[14];
    #pragma unroll
    for (int d = 0; d < 14; d++) {
        float e = ex2_approx((acc[d] + b2v) * LOG2E);
        ex[d] = e;
        float s = e;
        #pragma unroll
        for (int off = 16; off; off >>= 1)
            s += __shfl_xor_sync(0xffffffffu, s, off);
        if (lane == 0) red[d * 16 + wid] = s;
    }
    __syncthreads();
    if (wid < 14) {
        float v = (lane < 16) ? red[wid * 16 + lane] : 0.f;
        #pragma unroll
        for (int off = 8; off; off >>= 1)
            v += __shfl_xor_sync(0xffffffffu, v, off);
        if (lane == 0) inv_sh[wid] = 1.0f / v;
    }
    __syncthreads();
    #pragma unroll
    for (int d = 0; d < 14; d++) {
        if (d0 + d < 512)
            out[((size_t)(b << 9) + d0 + d) * 512 + t] = ex[d] * inv_sh[d];
    }
}

// ---------------------------------------------------------------------------
extern "C" void kernel_launch(void* const* d_in, const int* in_sizes, int n_in,
                              void* d_out, int out_size)
{
    const float* ctx  = (const float*)d_in[0];
    const float* dec  = (const float*)d_in[1];
    const float* W1i  = (const float*)d_in[2];
    const float* b1i  = (const float*)d_in[3];
    const float* W1h  = (const float*)d_in[4];
    const float* b1h  = (const float*)d_in[5];
    const float* w2   = (const float*)d_in[6];
    const float* b2   = (const float*)d_in[7];
    float* out = (float*)d_out;

    kernelA<<<129, 256>>>(ctx, dec, W1i, b1i, W1h, b1h);
    kernelB<<<148, 512>>>(w2, b2, out);
}

// round 2
// speedup vs baseline: 1.3211x; 1.3211x over previous
#include <cuda_runtime.h>
#include <cuda_bf16.h>

// ---------------------------------------------------------------------------
// PointerNet additive attention, B=4, Te=Td=512, E=256, D+E=512, H=64.
// out[b,d,t] = softmax_t( sum_h w2[h]*tanh(dec_t[b,d,h] + ctx_t[b,t,h]) + b2 )
//
// Kernel A: projections (raw, no pre-scale). ctx projection stored
//           TRANSPOSED [b][h][t] for coalesced reads in kernel B.
//           Fine-grained blocks (257) => ~2 blocks/SM for latency hiding.
// Kernel B: fused score + tanh.approx + H-reduction + softmax.
//           148 blocks = 1 full wave; single MUFU op per element.
// ---------------------------------------------------------------------------

#define B_   4
#define TE_  512
#define TD_  512
#define H_   64

#define LOG2E 1.4426950408889634f

// scratch (device globals: allocation-free)
__device__ float g_ctxT[B_ * H_ * TE_];   // [b][h][t]
__device__ float g_decS[B_ * TD_ * H_];   // [b*Td+d][h]

// ---------------------------------------------------------------------------
// Kernel A: fused projections.
//   blocks [0,86):   ctx rows, 24 rows/block, K=256
//   blocks [86,257): dec rows, 12 rows/block, K=512
// 256 threads: h = tid&63, row-group rg = tid>>6 (4 groups)
// ---------------------------------------------------------------------------
__global__ __launch_bounds__(256) void kernelA(
    const float* __restrict__ ctx,   // [4,512,256]
    const float* __restrict__ dec,   // [4,512,512]
    const float* __restrict__ W1i,   // [256,64]
    const float* __restrict__ b1i,   // [64]
    const float* __restrict__ W1h,   // [512,64]
    const float* __restrict__ b1h)   // [64]
{
    __shared__ float xs[6144];                        // 24KB tile (union)
    float4* xs4 = reinterpret_cast<float4*>(xs);

    const int tid = threadIdx.x;
    const int h   = tid & 63;
    const int rg  = tid >> 6;

    if (blockIdx.x < 86) {
        // ----- ctx projection: 24 rows of K=256 -----
        const int r0 = blockIdx.x * 24;
        const float4* src = reinterpret_cast<const float4*>(ctx);
        for (int i = tid; i < 24 * 64; i += 256) {     // 64 float4 per row
            int row = i >> 6;
            xs4[i] = (r0 + row < 2048) ? src[(size_t)(r0 + row) * 64 + (i & 63)]
                                       : make_float4(0.f, 0.f, 0.f, 0.f);
        }
        __syncthreads();

        float acc[6];
        #pragma unroll
        for (int r = 0; r < 6; r++) acc[r] = 0.f;

        for (int e = 0; e < 256; e += 4) {
            const float* wp = W1i + e * 64 + h;
            float w0 = wp[0], w1 = wp[64], w2v = wp[128], w3 = wp[192];
            #pragma unroll
            for (int r = 0; r < 6; r++) {
                float4 x = xs4[(rg * 6 + r) * 64 + (e >> 2)];
                acc[r] = fmaf(x.x, w0, acc[r]);
                acc[r] = fmaf(x.y, w1, acc[r]);
                acc[r] = fmaf(x.z, w2v, acc[r]);
                acc[r] = fmaf(x.w, w3, acc[r]);
            }
        }
        const float bias = b1i[h];
        #pragma unroll
        for (int r = 0; r < 6; r++) {
            int row = r0 + rg * 6 + r;
            if (row < 2048) {
                int b = row >> 9, t = row & 511;
                g_ctxT[((b << 6) + h) * 512 + t] = acc[r] + bias;
            }
        }
    } else {
        // ----- dec projection: 12 rows of K=512 -----
        const int r0 = (blockIdx.x - 86) * 12;
        const float4* src = reinterpret_cast<const float4*>(dec);
        for (int i = tid; i < 12 * 128; i += 256) {    // 128 float4 per row
            int row = i >> 7;
            xs4[i] = (r0 + row < 2048) ? src[(size_t)(r0 + row) * 128 + (i & 127)]
                                       : make_float4(0.f, 0.f, 0.f, 0.f);
        }
        __syncthreads();

        float acc[3];
        #pragma unroll
        for (int r = 0; r < 3; r++) acc[r] = 0.f;

        for (int e = 0; e < 512; e += 4) {
            const float* wp = W1h + e * 64 + h;
            float w0 = wp[0], w1 = wp[64], w2v = wp[128], w3 = wp[192];
            #pragma unroll
            for (int r = 0; r < 3; r++) {
                float4 x = xs4[(rg * 3 + r) * 128 + (e >> 2)];
                acc[r] = fmaf(x.x, w0, acc[r]);
                acc[r] = fmaf(x.y, w1, acc[r]);
                acc[r] = fmaf(x.z, w2v, acc[r]);
                acc[r] = fmaf(x.w, w3, acc[r]);
            }
        }
        const float bias = b1h[h];
        #pragma unroll
        for (int r = 0; r < 3; r++) {
            int row = r0 + rg * 3 + r;
            if (row < 2048)
                g_decS[(size_t)row * 64 + h] = acc[r] + bias;
        }
    }
}

// ---------------------------------------------------------------------------
// Kernel B: fused tanh-score + softmax.
// grid = 148 (4 batches x 37 d-tiles of 14, last tile has 8 valid rows).
// 512 threads: thread t owns encoder column t for all 14 decoder rows.
// ---------------------------------------------------------------------------
__device__ __forceinline__ float ex2_approx(float x) {
    float y; asm("ex2.approx.f32 %0, %1;" : "=f"(y) : "f"(x)); return y;
}
__device__ __forceinline__ float tanh_approx(float x) {
    float y; asm("tanh.approx.f32 %0, %1;" : "=f"(y) : "f"(x)); return y;
}

__global__ __launch_bounds__(512) void kernelB(
    const float* __restrict__ w2,    // [64]
    const float* __restrict__ b2p,   // [1]
    float* __restrict__ out)         // [4,512,512]
{
    __shared__ float dec_sh[14 * 64];
    __shared__ float w2_sh[64];
    __shared__ float red[14 * 16];
    __shared__ float inv_sh[14];

    const int tid = threadIdx.x;
    const int b   = blockIdx.x / 37;
    const int ti  = blockIdx.x % 37;
    const int d0  = ti * 14;

    // load decoder tile (zero-fill past batch end) + w2
    for (int i = tid; i < 14 * 64; i += 512) {
        int r = i >> 6;
        dec_sh[i] = (d0 + r < 512) ? g_decS[((size_t)(b << 9) + d0) * 64 + i] : 0.f;
    }
    if (tid < 64) w2_sh[tid] = w2[tid];
    __syncthreads();

    const int t = tid;
    const float* cptr = g_ctxT + (size_t)(b << 6) * 512 + t;

    float acc[14];
    #pragma unroll
    for (int d = 0; d < 14; d++) acc[d] = 0.f;

    #pragma unroll 1
    for (int h = 0; h < 64; h += 4) {
        float c0 = cptr[(h + 0) * 512];
        float c1 = cptr[(h + 1) * 512];
        float c2 = cptr[(h + 2) * 512];
        float c3 = cptr[(h + 3) * 512];
        float4 w4 = *reinterpret_cast<const float4*>(&w2_sh[h]);
        #pragma unroll
        for (int d = 0; d < 14; d++) {
            float4 dv = *reinterpret_cast<const float4*>(&dec_sh[d * 64 + h]);
            acc[d] = fmaf(w4.x, tanh_approx(dv.x + c0), acc[d]);
            acc[d] = fmaf(w4.y, tanh_approx(dv.y + c1), acc[d]);
            acc[d] = fmaf(w4.z, tanh_approx(dv.z + c2), acc[d]);
            acc[d] = fmaf(w4.w, tanh_approx(dv.w + c3), acc[d]);
        }
    }

    // softmax over t (scores bounded by sum|w2| ~ 6, no max-shift needed)
    const float b2v = b2p[0];
    const int wid = tid >> 5, lane = tid & 31;
    float ex[14];
    #pragma unroll
    for (int d = 0; d < 14; d++) {
        float e = ex2_approx((acc[d] + b2v) * LOG2E);
        ex[d] = e;
        float s = e;
        #pragma unroll
        for (int off = 16; off; off >>= 1)
            s += __shfl_xor_sync(0xffffffffu, s, off);
        if (lane == 0) red[d * 16 + wid] = s;
    }
    __syncthreads();
    if (wid < 14) {
        float v = (lane < 16) ? red[wid * 16 + lane] : 0.f;
        #pragma unroll
        for (int off = 8; off; off >>= 1)
            v += __shfl_xor_sync(0xffffffffu, v, off);
        if (lane == 0) inv_sh[wid] = 1.0f / v;
    }
    __syncthreads();
    #pragma unroll
    for (int d = 0; d < 14; d++) {
        if (d0 + d < 512)
            out[((size_t)(b << 9) + d0 + d) * 512 + t] = ex[d] * inv_sh[d];
    }
}

// ---------------------------------------------------------------------------
extern "C" void kernel_launch(void* const* d_in, const int* in_sizes, int n_in,
                              void* d_out, int out_size)
{
    const float* ctx  = (const float*)d_in[0];
    const float* dec  = (const float*)d_in[1];
    const float* W1i  = (const float*)d_in[2];
    const float* b1i  = (const float*)d_in[3];
    const float* W1h  = (const float*)d_in[4];
    const float* b1h  = (const float*)d_in[5];
    const float* w2   = (const float*)d_in[6];
    const float* b2   = (const float*)d_in[7];
    float* out = (float*)d_out;

    kernelA<<<257, 256>>>(ctx, dec, W1i, b1i, W1h, b1h);
    kernelB<<<148, 512>>>(w2, b2, out);
}

// round 3
// speedup vs baseline: 1.7585x; 1.3311x over previous
#include <cuda_runtime.h>
#include <cuda_bf16.h>

// ---------------------------------------------------------------------------
// PointerNet additive attention, B=4, Te=Td=512, E=256, D+E=512, H=64.
// out[b,d,t] = softmax_t( sum_h w2[h]*tanh(dec_t[b,d,h] + ctx_t[b,t,h]) + b2 )
//
// Kernel A: projections, split-K across warps (each warp owns an e-range,
//           lanes own h-pairs) -> 8-16x fewer weight LDGs. smem partials
//           reduced after the mainloop (buffer reused). ctx output stored
//           TRANSPOSED [b][h][t] for coalesced reads in kernel B.
// Kernel B: fused score + tanh.approx + H-reduction + softmax.
//           7-row tiles, 296 blocks = 2 blocks/SM for latency hiding.
// ---------------------------------------------------------------------------

#define B_   4
#define TE_  512
#define TD_  512
#define H_   64

#define LOG2E 1.4426950408889634f

// scratch (device globals: allocation-free)
__device__ float g_ctxT[B_ * H_ * TE_];   // [b][h][t]
__device__ float g_decS[B_ * TD_ * H_];   // [b*Td+d][h]

// ---------------------------------------------------------------------------
// Kernel A: projections, 256 blocks x 256 threads.
//   blocks [0,128):   ctx rows, 16 rows/block, K=256 (warp e-range 32)
//   blocks [128,256): dec rows, 16 rows/block, K=512 (warp e-range 64)
// Warp w handles e in [w*EW, (w+1)*EW); lane owns h = {2*lane, 2*lane+1}.
// Partials: buf[w][r][h] (8*16*64 floats = 32KB), reduced by all threads.
// ---------------------------------------------------------------------------
__global__ __launch_bounds__(256) void kernelA(
    const float* __restrict__ ctx,   // [4,512,256]
    const float* __restrict__ dec,   // [4,512,512]
    const float* __restrict__ W1i,   // [256,64]
    const float* __restrict__ b1i,   // [64]
    const float* __restrict__ W1h,   // [512,64]
    const float* __restrict__ b1h)   // [64]
{
    __shared__ float buf[8192];                       // 32KB: x tile, then partials
    float4* buf4 = reinterpret_cast<float4*>(buf);

    const int tid  = threadIdx.x;
    const int wid  = tid >> 5;
    const int lane = tid & 31;

    const bool is_ctx = (blockIdx.x < 128);
    const int  E      = is_ctx ? 256 : 512;
    const int  EW     = E >> 3;                       // e-range per warp
    const int  r0     = (is_ctx ? blockIdx.x : (blockIdx.x - 128)) * 16;
    const float* W    = is_ctx ? W1i : W1h;
    const float* bias = is_ctx ? b1i : b1h;
    const float* X    = is_ctx ? ctx : dec;

    // ---- load x tile [16][E] coalesced (no bounds needed: 128*16 = 2048) ----
    {
        const float4* src = reinterpret_cast<const float4*>(X);
        const int nf4 = 16 * (E >> 2);
        const int lg2 = is_ctx ? 6 : 7;               // float4s per row
        const int msk = (1 << lg2) - 1;
        for (int i = tid; i < nf4; i += 256)
            buf4[i] = src[(size_t)(r0 + (i >> lg2)) * (E >> 2) + (i & msk)];
    }
    __syncthreads();

    // ---- mainloop: warp-private e-range, per-lane h-pair ----
    float acc0[16], acc1[16];
    #pragma unroll
    for (int r = 0; r < 16; r++) { acc0[r] = 0.f; acc1[r] = 0.f; }

    const int e0 = wid * EW;
    const float* wbase = W + (size_t)e0 * 64 + 2 * lane;

    #pragma unroll 1
    for (int ec = 0; ec < EW; ec += 4) {
        float2 w0 = *reinterpret_cast<const float2*>(wbase + (ec + 0) * 64);
        float2 w1 = *reinterpret_cast<const float2*>(wbase + (ec + 1) * 64);
        float2 w2v = *reinterpret_cast<const float2*>(wbase + (ec + 2) * 64);
        float2 w3 = *reinterpret_cast<const float2*>(wbase + (ec + 3) * 64);
        #pragma unroll
        for (int r = 0; r < 16; r++) {
            float4 x = *reinterpret_cast<const float4*>(&buf[r * E + e0 + ec]);
            float a0 = acc0[r], a1 = acc1[r];
            a0 = fmaf(x.x, w0.x, a0);  a1 = fmaf(x.x, w0.y, a1);
            a0 = fmaf(x.y, w1.x, a0);  a1 = fmaf(x.y, w1.y, a1);
            a0 = fmaf(x.z, w2v.x, a0); a1 = fmaf(x.z, w2v.y, a1);
            a0 = fmaf(x.w, w3.x, a0);  a1 = fmaf(x.w, w3.y, a1);
            acc0[r] = a0; acc1[r] = a1;
        }
    }

    // ---- partials into smem (reuse buf) ----
    __syncthreads();
    #pragma unroll
    for (int r = 0; r < 16; r++) {
        float2 v = make_float2(acc0[r], acc1[r]);
        *reinterpret_cast<float2*>(&buf[wid * 1024 + r * 64 + 2 * lane]) = v;
    }
    __syncthreads();

    // ---- reduce 8 partials; each thread owns 4 consecutive outputs ----
    {
        const int o = tid * 4;                        // o = r*64 + h, h%4==0
        const int r = o >> 6;
        const int h = o & 63;
        float4 s = make_float4(0.f, 0.f, 0.f, 0.f);
        #pragma unroll
        for (int w = 0; w < 8; w++) {
            float4 p = *reinterpret_cast<const float4*>(&buf[w * 1024 + o]);
            s.x += p.x; s.y += p.y; s.z += p.z; s.w += p.w;
        }
        float4 bv = *reinterpret_cast<const float4*>(bias + h);
        s.x += bv.x; s.y += bv.y; s.z += bv.z; s.w += bv.w;

        const int row = r0 + r;
        if (is_ctx) {
            const int b = row >> 9, t = row & 511;
            float* dst = g_ctxT + ((size_t)(b << 6)) * 512 + t;
            dst[(h + 0) * 512] = s.x;
            dst[(h + 1) * 512] = s.y;
            dst[(h + 2) * 512] = s.z;
            dst[(h + 3) * 512] = s.w;
        } else {
            *reinterpret_cast<float4*>(&g_decS[(size_t)row * 64 + h]) = s;
        }
    }
}

// ---------------------------------------------------------------------------
// Kernel B: fused tanh-score + softmax.
// grid = 296 (4 batches x 74 d-tiles of 7) => 2 blocks/SM.
// 512 threads: thread t owns encoder column t for all 7 decoder rows.
// ---------------------------------------------------------------------------
__device__ __forceinline__ float ex2_approx(float x) {
    float y; asm("ex2.approx.f32 %0, %1;" : "=f"(y) : "f"(x)); return y;
}
__device__ __forceinline__ float tanh_approx(float x) {
    float y; asm("tanh.approx.f32 %0, %1;" : "=f"(y) : "f"(x)); return y;
}

__global__ __launch_bounds__(512) void kernelB(
    const float* __restrict__ w2,    // [64]
    const float* __restrict__ b2p,   // [1]
    float* __restrict__ out)         // [4,512,512]
{
    __shared__ float dec_sh[7 * 64];
    __shared__ float w2_sh[64];
    __shared__ float red[7 * 16];
    __shared__ float inv_sh[7];

    const int tid = threadIdx.x;
    const int b   = blockIdx.x / 74;
    const int ti  = blockIdx.x % 74;
    const int d0  = ti * 7;

    // load decoder tile (zero-fill past batch end) + w2
    if (tid < 7 * 64) {
        int r = tid >> 6;
        dec_sh[tid] = (d0 + r < 512) ? g_decS[((size_t)(b << 9) + d0) * 64 + tid] : 0.f;
    }
    if (tid >= 448 && tid < 512) w2_sh[tid - 448] = w2[tid - 448];
    __syncthreads();

    const int t = tid;
    const float* cptr = g_ctxT + (size_t)(b << 6) * 512 + t;

    float acc[7];
    #pragma unroll
    for (int d = 0; d < 7; d++) acc[d] = 0.f;

    #pragma unroll 1
    for (int h = 0; h < 64; h += 4) {
        float c0 = cptr[(h + 0) * 512];
        float c1 = cptr[(h + 1) * 512];
        float c2 = cptr[(h + 2) * 512];
        float c3 = cptr[(h + 3) * 512];
        float4 w4 = *reinterpret_cast<const float4*>(&w2_sh[h]);
        #pragma unroll
        for (int d = 0; d < 7; d++) {
            float4 dv = *reinterpret_cast<const float4*>(&dec_sh[d * 64 + h]);
            acc[d] = fmaf(w4.x, tanh_approx(dv.x + c0), acc[d]);
            acc[d] = fmaf(w4.y, tanh_approx(dv.y + c1), acc[d]);
            acc[d] = fmaf(w4.z, tanh_approx(dv.z + c2), acc[d]);
            acc[d] = fmaf(w4.w, tanh_approx(dv.w + c3), acc[d]);
        }
    }

    // softmax over t (scores bounded by sum|w2| ~ 6, no max-shift needed)
    const float b2v = b2p[0];
    const int wid = tid >> 5, lane = tid & 31;
    float ex[7];
    #pragma unroll
    for (int d = 0; d < 7; d++) {
        float e = ex2_approx((acc[d] + b2v) * LOG2E);
        ex[d] = e;
        float s = e;
        #pragma unroll
        for (int off = 16; off; off >>= 1)
            s += __shfl_xor_sync(0xffffffffu, s, off);
        if (lane == 0) red[d * 16 + wid] = s;
    }
    __syncthreads();
    if (wid < 7) {
        float v = (lane < 16) ? red[wid * 16 + lane] : 0.f;
        #pragma unroll
        for (int off = 8; off; off >>= 1)
            v += __shfl_xor_sync(0xffffffffu, v, off);
        if (lane == 0) inv_sh[wid] = 1.0f / v;
    }
    __syncthreads();
    #pragma unroll
    for (int d = 0; d < 7; d++) {
        if (d0 + d < 512)
            out[((size_t)(b << 9) + d0 + d) * 512 + t] = ex[d] * inv_sh[d];
    }
}

// ---------------------------------------------------------------------------
extern "C" void kernel_launch(void* const* d_in, const int* in_sizes, int n_in,
                              void* d_out, int out_size)
{
    const float* ctx  = (const float*)d_in[0];
    const float* dec  = (const float*)d_in[1];
    const float* W1i  = (const float*)d_in[2];
    const float* b1i  = (const float*)d_in[3];
    const float* W1h  = (const float*)d_in[4];
    const float* b1h  = (const float*)d_in[5];
    const float* w2   = (const float*)d_in[6];
    const float* b2   = (const float*)d_in[7];
    float* out = (float*)d_out;

    kernelA<<<256, 256>>>(ctx, dec, W1i, b1i, W1h, b1h);
    kernelB<<<296, 512>>>(w2, b2, out);
}

// round 4
// speedup vs baseline: 1.8354x; 1.0437x over previous
#include <cuda_runtime.h>
#include <cuda_bf16.h>

// ---------------------------------------------------------------------------
// PointerNet additive attention, B=4, Te=Td=512, E=256, D+E=512, H=64.
// out[b,d,t] = softmax_t( sum_h w2[h]*tanh(dec_t[b,d,h] + ctx_t[b,t,h]) + b2 )
// (b2 cancels in the softmax and is dropped.)
//
// Kernel A: projections. Split-K: 16 e-subranges (2 per warp via half-warps),
//           lane owns an h-QUAD -> each LDS.128 feeds 16 FMA (smem crossbar
//           at half of FMA demand). half-warp partials combined by shfl,
//           8 warp partials reduced through smem. ctx output TRANSPOSED
//           [b][h][t] for coalesced kernel-B reads.
// Kernel B: fused score + tanh.approx + softmax, 296 blocks = 2/SM.
//           ctxT loads software-pipelined (prefetch next h-group).
// ---------------------------------------------------------------------------

#define B_   4
#define TE_  512
#define TD_  512
#define H_   64

#define LOG2E 1.4426950408889634f

// scratch (device globals: allocation-free)
__device__ float g_ctxT[B_ * H_ * TE_];   // [b][h][t]
__device__ float g_decS[B_ * TD_ * H_];   // [b*Td+d][h]

// ---------------------------------------------------------------------------
// Kernel A: projections, 256 blocks x 256 threads, 16 rows/block.
//   blocks [0,128):   ctx rows, K=256 (e-subrange 16)
//   blocks [128,256): dec rows, K=512 (e-subrange 32)
// Warp w covers e-subranges {2w, 2w+1} via half-warps; lane owns h-quad
// 4*(lane&15). Per 4-e step: 4 LDG.128 (weights), 16 LDS.128 (x, broadcast
// within half-warp), 256 warp-FMA.
// ---------------------------------------------------------------------------
__global__ __launch_bounds__(256) void kernelA(
    const float* __restrict__ ctx,   // [4,512,256]
    const float* __restrict__ dec,   // [4,512,512]
    const float* __restrict__ W1i,   // [256,64]
    const float* __restrict__ b1i,   // [64]
    const float* __restrict__ W1h,   // [512,64]
    const float* __restrict__ b1h)   // [64]
{
    __shared__ float buf[8192];                       // 32KB: x tile, then partials
    float4* buf4 = reinterpret_cast<float4*>(buf);

    const int tid  = threadIdx.x;
    const int wid  = tid >> 5;
    const int lane = tid & 31;
    const int hl   = (lane & 15) << 2;                // h-quad base
    const int half = lane >> 4;                       // e-subrange selector

    const bool is_ctx = (blockIdx.x < 128);
    const int  E      = is_ctx ? 256 : 512;
    const int  ESUB   = E >> 4;                       // 16 subranges
    const int  r0     = (is_ctx ? blockIdx.x : (blockIdx.x - 128)) * 16;
    const float* W    = is_ctx ? W1i : W1h;
    const float* bias = is_ctx ? b1i : b1h;
    const float* X    = is_ctx ? ctx : dec;

    // ---- load x tile [16][E] coalesced (exact tiling, no bounds) ----
    {
        const float4* src = reinterpret_cast<const float4*>(X);
        const int rowf4 = E >> 2;
        const int nf4   = 16 * rowf4;
        for (int i = tid; i < nf4; i += 256)
            buf4[i] = src[(size_t)r0 * rowf4 + i];
    }
    __syncthreads();

    // ---- mainloop ----
    float acc[16][4];
    #pragma unroll
    for (int r = 0; r < 16; r++)
        #pragma unroll
        for (int j = 0; j < 4; j++) acc[r][j] = 0.f;

    const int e0 = (wid * 2 + half) * ESUB;
    const float* wptr = W + (size_t)e0 * 64 + hl;

    #pragma unroll 1
    for (int ec = 0; ec < ESUB; ec += 4) {
        float4 w0 = *reinterpret_cast<const float4*>(wptr + (ec + 0) * 64);
        float4 w1 = *reinterpret_cast<const float4*>(wptr + (ec + 1) * 64);
        float4 w2v = *reinterpret_cast<const float4*>(wptr + (ec + 2) * 64);
        float4 w3 = *reinterpret_cast<const float4*>(wptr + (ec + 3) * 64);
        #pragma unroll
        for (int r = 0; r < 16; r++) {
            float4 x = *reinterpret_cast<const float4*>(&buf[r * E + e0 + ec]);
            acc[r][0] = fmaf(x.x, w0.x, acc[r][0]);
            acc[r][1] = fmaf(x.x, w0.y, acc[r][1]);
            acc[r][2] = fmaf(x.x, w0.z, acc[r][2]);
            acc[r][3] = fmaf(x.x, w0.w, acc[r][3]);
            acc[r][0] = fmaf(x.y, w1.x, acc[r][0]);
            acc[r][1] = fmaf(x.y, w1.y, acc[r][1]);
            acc[r][2] = fmaf(x.y, w1.z, acc[r][2]);
            acc[r][3] = fmaf(x.y, w1.w, acc[r][3]);
            acc[r][0] = fmaf(x.z, w2v.x, acc[r][0]);
            acc[r][1] = fmaf(x.z, w2v.y, acc[r][1]);
            acc[r][2] = fmaf(x.z, w2v.z, acc[r][2]);
            acc[r][3] = fmaf(x.z, w2v.w, acc[r][3]);
            acc[r][0] = fmaf(x.w, w3.x, acc[r][0]);
            acc[r][1] = fmaf(x.w, w3.y, acc[r][1]);
            acc[r][2] = fmaf(x.w, w3.z, acc[r][2]);
            acc[r][3] = fmaf(x.w, w3.w, acc[r][3]);
        }
    }

    // ---- combine half-warps (same h-quad, different e-subranges) ----
    #pragma unroll
    for (int r = 0; r < 16; r++)
        #pragma unroll
        for (int j = 0; j < 4; j++)
            acc[r][j] += __shfl_xor_sync(0xffffffffu, acc[r][j], 16);

    __syncthreads();                                  // x tile no longer needed
    if (half == 0) {
        #pragma unroll
        for (int r = 0; r < 16; r++)
            *reinterpret_cast<float4*>(&buf[wid * 1024 + r * 64 + hl]) =
                make_float4(acc[r][0], acc[r][1], acc[r][2], acc[r][3]);
    }
    __syncthreads();

    // ---- reduce 8 warp partials; each thread owns 4 consecutive outputs ----
    {
        const int o = tid * 4;                        // o = r*64 + h, h%4==0
        const int r = o >> 6;
        const int h = o & 63;
        float4 s = make_float4(0.f, 0.f, 0.f, 0.f);
        #pragma unroll
        for (int w = 0; w < 8; w++) {
            float4 p = *reinterpret_cast<const float4*>(&buf[w * 1024 + o]);
            s.x += p.x; s.y += p.y; s.z += p.z; s.w += p.w;
        }
        float4 bv = *reinterpret_cast<const float4*>(bias + h);
        s.x += bv.x; s.y += bv.y; s.z += bv.z; s.w += bv.w;

        const int row = r0 + r;
        if (is_ctx) {
            const int b = row >> 9, t = row & 511;
            float* dst = g_ctxT + ((size_t)(b << 6)) * 512 + t;
            dst[(h + 0) * 512] = s.x;
            dst[(h + 1) * 512] = s.y;
            dst[(h + 2) * 512] = s.z;
            dst[(h + 3) * 512] = s.w;
        } else {
            *reinterpret_cast<float4*>(&g_decS[(size_t)row * 64 + h]) = s;
        }
    }
}

// ---------------------------------------------------------------------------
// Kernel B: fused tanh-score + softmax.
// grid = 296 (4 batches x 74 d-tiles of 7) => 2 blocks/SM.
// 512 threads: thread t owns encoder column t for all 7 decoder rows.
// ctxT loads are prefetched one h-group ahead to hide L2 latency.
// ---------------------------------------------------------------------------
__device__ __forceinline__ float ex2_approx(float x) {
    float y; asm("ex2.approx.f32 %0, %1;" : "=f"(y) : "f"(x)); return y;
}
__device__ __forceinline__ float tanh_approx(float x) {
    float y; asm("tanh.approx.f32 %0, %1;" : "=f"(y) : "f"(x)); return y;
}

__global__ __launch_bounds__(512) void kernelB(
    const float* __restrict__ w2,    // [64]
    float* __restrict__ out)         // [4,512,512]
{
    __shared__ float dec_sh[7 * 64];
    __shared__ float w2_sh[64];      // pre-scaled by log2(e)
    __shared__ float red[7 * 16];
    __shared__ float inv_sh[7];

    const int tid = threadIdx.x;
    const int b   = blockIdx.x / 74;
    const int ti  = blockIdx.x % 74;
    const int d0  = ti * 7;

    // load decoder tile (zero-fill past batch end) + w2*log2e
    if (tid < 448) {
        int r = tid >> 6;
        dec_sh[tid] = (d0 + r < 512) ? g_decS[((size_t)(b << 9) + d0) * 64 + tid] : 0.f;
    } else {
        w2_sh[tid - 448] = w2[tid - 448] * LOG2E;
    }
    __syncthreads();

    const float* cptr = g_ctxT + (size_t)(b << 6) * 512 + tid;

    float acc[7];
    #pragma unroll
    for (int d = 0; d < 7; d++) acc[d] = 0.f;

    // prime the pipeline with h-group 0
    float c0 = cptr[0 * 512];
    float c1 = cptr[1 * 512];
    float c2 = cptr[2 * 512];
    float c3 = cptr[3 * 512];

    #pragma unroll 1
    for (int h = 0; h < 64; h += 4) {
        // prefetch next group (wrap &63 on last iter: in-bounds, cached, unused)
        const int hn = (h + 4) & 63;
        float n0 = cptr[(hn + 0) * 512];
        float n1 = cptr[(hn + 1) * 512];
        float n2 = cptr[(hn + 2) * 512];
        float n3 = cptr[(hn + 3) * 512];

        float4 w4 = *reinterpret_cast<const float4*>(&w2_sh[h]);
        #pragma unroll
        for (int d = 0; d < 7; d++) {
            float4 dv = *reinterpret_cast<const float4*>(&dec_sh[d * 64 + h]);
            acc[d] = fmaf(w4.x, tanh_approx(dv.x + c0), acc[d]);
            acc[d] = fmaf(w4.y, tanh_approx(dv.y + c1), acc[d]);
            acc[d] = fmaf(w4.z, tanh_approx(dv.z + c2), acc[d]);
            acc[d] = fmaf(w4.w, tanh_approx(dv.w + c3), acc[d]);
        }
        c0 = n0; c1 = n1; c2 = n2; c3 = n3;
    }

    // softmax over t (acc already in log2 domain; b2 cancels and is dropped;
    // scores bounded by sum|w2| ~ 6 => no max-shift needed)
    const int wid = tid >> 5, lane = tid & 31;
    float ex[7];
    #pragma unroll
    for (int d = 0; d < 7; d++) {
        float e = ex2_approx(acc[d]);
        ex[d] = e;
        float s = e;
        #pragma unroll
        for (int off = 16; off; off >>= 1)
            s += __shfl_xor_sync(0xffffffffu, s, off);
        if (lane == 0) red[d * 16 + wid] = s;
    }
    __syncthreads();
    if (wid < 7) {
        float v = (lane < 16) ? red[wid * 16 + lane] : 0.f;
        #pragma unroll
        for (int off = 8; off; off >>= 1)
            v += __shfl_xor_sync(0xffffffffu, v, off);
        if (lane == 0) inv_sh[wid] = 1.0f / v;
    }
    __syncthreads();
    #pragma unroll
    for (int d = 0; d < 7; d++) {
        if (d0 + d < 512)
            out[((size_t)(b << 9) + d0 + d) * 512 + tid] = ex[d] * inv_sh[d];
    }
}

// ---------------------------------------------------------------------------
extern "C" void kernel_launch(void* const* d_in, const int* in_sizes, int n_in,
                              void* d_out, int out_size)
{
    const float* ctx  = (const float*)d_in[0];
    const float* dec  = (const float*)d_in[1];
    const float* W1i  = (const float*)d_in[2];
    const float* b1i  = (const float*)d_in[3];
    const float* W1h  = (const float*)d_in[4];
    const float* b1h  = (const float*)d_in[5];
    const float* w2   = (const float*)d_in[6];
    float* out = (float*)d_out;

    kernelA<<<256, 256>>>(ctx, dec, W1i, b1i, W1h, b1h);
    kernelB<<<296, 512>>>(w2, out);
}